// round 16
// baseline (speedup 1.0000x reference)
#include <cuda_runtime.h>
#include <math.h>

#define N_BINS 1024
#define N_COPIES 8           // one PRIVATE smem histogram per warp (256 thr / 32)
#define HIST_BLOCKS 592      // 4 * 148 SMs — established optimum (32 warps/SM)
#define HIST_THREADS 256

__device__ unsigned int g_counts[N_BINS];     // zero at load; reset each run below
__device__ unsigned int g_done;               // arrival counter, reset each run

__global__ void __launch_bounds__(HIST_THREADS) hist_kernel(
    const int* __restrict__ idx, long long n, float inv_n,
    float* __restrict__ out)
{
    __shared__ __align__(16) unsigned int sh[N_COPIES][N_BINS];
    __shared__ bool s_last;
    __shared__ float red[HIST_THREADS / 32];

    // vectorized zero: 2048 STS.128 per block (was 8192 STS.32)
    uint4* flat4 = (uint4*)&sh[0][0];
    #pragma unroll
    for (int i = 0; i < (N_COPIES * N_BINS / 4) / HIST_THREADS; i++)
        flat4[threadIdx.x + i * HIST_THREADS] = make_uint4(0u, 0u, 0u, 0u);
    __syncthreads();

    unsigned int* h = sh[threadIdx.x >> 5];   // fully private per-warp copy

    long long tid    = (long long)blockIdx.x * blockDim.x + threadIdx.x;
    long long stride = (long long)gridDim.x * blockDim.x;
    long long n4     = n >> 2;
    const int4* p4   = (const int4*)idx;

    // Indices are randint(0, 1024) by problem construction: no mask needed.
    // Mainloop: 2 outstanding int4 loads per iteration (R15's exact body).
    long long i = tid;
    for (; i + stride < n4; i += 2 * stride) {
        int4 a = p4[i];
        int4 b = p4[i + stride];
        atomicAdd(&h[a.x], 1u);
        atomicAdd(&h[a.y], 1u);
        atomicAdd(&h[a.z], 1u);
        atomicAdd(&h[a.w], 1u);
        atomicAdd(&h[b.x], 1u);
        atomicAdd(&h[b.y], 1u);
        atomicAdd(&h[b.z], 1u);
        atomicAdd(&h[b.w], 1u);
    }
    for (; i < n4; i += stride) {
        int4 a = p4[i];
        atomicAdd(&h[a.x], 1u);
        atomicAdd(&h[a.y], 1u);
        atomicAdd(&h[a.z], 1u);
        atomicAdd(&h[a.w], 1u);
    }
    // remainder (n not multiple of 4)
    for (long long r = (n4 << 2) + tid; r < n; r += stride)
        atomicAdd(&h[idx[r]], 1u);

    __syncthreads();

    // flush per-warp copies -> global histogram (established form)
    for (int b = threadIdx.x; b < N_BINS; b += blockDim.x) {
        unsigned int s = 0;
        #pragma unroll
        for (int c = 0; c < N_COPIES; c++) s += sh[c][b];
        atomicAdd(&g_counts[b], s);
    }

    // last-block-done: fused finalize (established form)
    __threadfence();
    if (threadIdx.x == 0)
        s_last = (atomicAdd(&g_done, 1u) == (unsigned)(gridDim.x - 1));
    __syncthreads();

    if (s_last) {
        int t = threadIdx.x;
        volatile unsigned int* gc = g_counts;
        float v = 0.0f;
        #pragma unroll
        for (int k = 0; k < N_BINS / HIST_THREADS; k++) {
            int b = t + k * HIST_THREADS;
            unsigned int c = gc[b];
            g_counts[b] = 0u;                 // reset for next replay
            float p = (float)c * inv_n;
            v += p * logf(p + 1e-8f);
        }
        #pragma unroll
        for (int o = 16; o > 0; o >>= 1) v += __shfl_down_sync(0xFFFFFFFFu, v, o);
        if ((t & 31) == 0) red[t >> 5] = v;
        __syncthreads();
        if (t < 32) {
            float s = (t < HIST_THREADS / 32) ? red[t] : 0.0f;
            #pragma unroll
            for (int o = 4; o > 0; o >>= 1) s += __shfl_down_sync(0xFFFFFFFFu, s, o);
            if (t == 0) {
                out[0] = expf(-s);
                g_done = 0u;                  // reset arrival counter for next replay
            }
        }
    }
}

extern "C" void kernel_launch(void* const* d_in, const int* in_sizes, int n_in,
                              void* d_out, int out_size) {
    const int* idx = (const int*)d_in[0];
    long long n    = (long long)in_sizes[0];
    float* out     = (float*)d_out;

    hist_kernel<<<HIST_BLOCKS, HIST_THREADS>>>(idx, n, 1.0f / (float)n, out);
}

// round 17
// speedup vs baseline: 1.0152x; 1.0152x over previous
#include <cuda_runtime.h>
#include <math.h>

#define N_BINS 1024
#define N_COPIES 8           // one PRIVATE smem histogram per warp (256 thr / 32)
#define HIST_BLOCKS 592      // 4 * 148 SMs — established optimum (32 warps/SM)
#define HIST_THREADS 256

__device__ unsigned int g_counts[N_BINS];     // zero at load; reset each run below
__device__ unsigned int g_done;               // arrival counter, reset each run

__global__ void __launch_bounds__(HIST_THREADS) hist_kernel(
    const int* __restrict__ idx, long long n, float inv_n,
    float* __restrict__ out)
{
    __shared__ unsigned int sh[N_COPIES][N_BINS];
    __shared__ bool s_last;
    __shared__ float red[HIST_THREADS / 32];

    unsigned int* flat = &sh[0][0];
    for (int i = threadIdx.x; i < N_COPIES * N_BINS; i += blockDim.x)
        flat[i] = 0u;
    __syncthreads();

    unsigned int* h = sh[threadIdx.x >> 5];   // fully private per-warp copy

    long long tid    = (long long)blockIdx.x * blockDim.x + threadIdx.x;
    long long stride = (long long)gridDim.x * blockDim.x;
    long long n4     = n >> 2;
    const int4* p4   = (const int4*)idx;

    // Indices are randint(0, 1024) by problem construction: no mask needed.
    // Mainloop: 4 outstanding int4 loads per iteration (MLP4 — the one
    // untested-in-isolation axis; loads hidden behind the 16-ATOMS drain).
    long long i = tid;
    for (; i + 3 * stride < n4; i += 4 * stride) {
        int4 a = p4[i];
        int4 b = p4[i + stride];
        int4 c = p4[i + 2 * stride];
        int4 d = p4[i + 3 * stride];
        atomicAdd(&h[a.x], 1u);
        atomicAdd(&h[a.y], 1u);
        atomicAdd(&h[a.z], 1u);
        atomicAdd(&h[a.w], 1u);
        atomicAdd(&h[b.x], 1u);
        atomicAdd(&h[b.y], 1u);
        atomicAdd(&h[b.z], 1u);
        atomicAdd(&h[b.w], 1u);
        atomicAdd(&h[c.x], 1u);
        atomicAdd(&h[c.y], 1u);
        atomicAdd(&h[c.z], 1u);
        atomicAdd(&h[c.w], 1u);
        atomicAdd(&h[d.x], 1u);
        atomicAdd(&h[d.y], 1u);
        atomicAdd(&h[d.z], 1u);
        atomicAdd(&h[d.w], 1u);
    }
    for (; i < n4; i += stride) {
        int4 a = p4[i];
        atomicAdd(&h[a.x], 1u);
        atomicAdd(&h[a.y], 1u);
        atomicAdd(&h[a.z], 1u);
        atomicAdd(&h[a.w], 1u);
    }
    // remainder (n not multiple of 4)
    for (long long r = (n4 << 2) + tid; r < n; r += stride)
        atomicAdd(&h[idx[r]], 1u);

    __syncthreads();

    // flush per-warp copies -> global histogram (established form)
    for (int b = threadIdx.x; b < N_BINS; b += blockDim.x) {
        unsigned int s = 0;
        #pragma unroll
        for (int c = 0; c < N_COPIES; c++) s += sh[c][b];
        atomicAdd(&g_counts[b], s);
    }

    // last-block-done: fused finalize (established form)
    __threadfence();
    if (threadIdx.x == 0)
        s_last = (atomicAdd(&g_done, 1u) == (unsigned)(gridDim.x - 1));
    __syncthreads();

    if (s_last) {
        int t = threadIdx.x;
        volatile unsigned int* gc = g_counts;
        float v = 0.0f;
        #pragma unroll
        for (int k = 0; k < N_BINS / HIST_THREADS; k++) {
            int b = t + k * HIST_THREADS;
            unsigned int c = gc[b];
            g_counts[b] = 0u;                 // reset for next replay
            float p = (float)c * inv_n;
            v += p * logf(p + 1e-8f);
        }
        #pragma unroll
        for (int o = 16; o > 0; o >>= 1) v += __shfl_down_sync(0xFFFFFFFFu, v, o);
        if ((t & 31) == 0) red[t >> 5] = v;
        __syncthreads();
        if (t < 32) {
            float s = (t < HIST_THREADS / 32) ? red[t] : 0.0f;
            #pragma unroll
            for (int o = 4; o > 0; o >>= 1) s += __shfl_down_sync(0xFFFFFFFFu, s, o);
            if (t == 0) {
                out[0] = expf(-s);
                g_done = 0u;                  // reset arrival counter for next replay
            }
        }
    }
}

extern "C" void kernel_launch(void* const* d_in, const int* in_sizes, int n_in,
                              void* d_out, int out_size) {
    const int* idx = (const int*)d_in[0];
    long long n    = (long long)in_sizes[0];
    float* out     = (float*)d_out;

    hist_kernel<<<HIST_BLOCKS, HIST_THREADS>>>(idx, n, 1.0f / (float)n, out);
}